// round 14
// baseline (speedup 1.0000x reference)
#include <cuda_runtime.h>
#include <cstdint>

// ---------------------------------------------------------------------------
// WindowAttention (Swin-style), GB300 sm_103a — fused kernel, R14.
// Head-decoupled (R13) +:
//  - P1 warp grid 2x2 per head (A-fragment LDS halved vs R13)
//  - P matrix never touches smem (c-frag -> a-frag via in-warp shfl, R9-
//    validated); phase-D stores, E loads, and one named barrier removed.
// Full syncs: 2. Named per-head: 1.
// Weights fragment-linear in global (coalesced LDG.64 per B-fragment).
// ---------------------------------------------------------------------------

__device__ uint32_t g_wqkvF[48 * 16 * 64];   // head-major [n8'][step][lane*2]
__device__ uint32_t g_woutF[16 * 16 * 64];

__device__ __forceinline__ uint32_t f2tf(float f) {
    uint32_t r;
    asm("cvt.rna.tf32.f32 %0, %1;" : "=r"(r) : "f"(f));
    return r;
}

__device__ __forceinline__ void mma8(float* c, const uint32_t* a, const uint32_t* b) {
    asm volatile(
        "mma.sync.aligned.m16n8k8.row.col.f32.tf32.tf32.f32 "
        "{%0,%1,%2,%3}, {%4,%5,%6,%7}, {%8,%9}, {%0,%1,%2,%3};\n"
        : "+f"(c[0]), "+f"(c[1]), "+f"(c[2]), "+f"(c[3])
        : "r"(a[0]), "r"(a[1]), "r"(a[2]), "r"(a[3]), "r"(b[0]), "r"(b[1]));
}
// slot within an 8-wide k-group: [k0 k4 k1 k5 k2 k6 k3 k7]
__device__ __forceinline__ int SL(int c) { return ((c & 3) << 1) | (c >> 2); }

// ===========================================================================
// cvt: weights -> tf32 fragment-linear.
// wqkv: HEAD-MAJOR permutation. n8' = h*12 + p  (p: 0-3 Q, 4-7 K, 8-11 V).
//   element (n8', step, lane, j): n_orig = seg*128 + h*32 + (p&3)*8 + lane>>2
//                                 k      = step*8 + (lane&3) + 4*j
// wout: unchanged fragment-linear.
// ===========================================================================
__global__ void cvt_kernel(const float* __restrict__ wqkv,
                           const float* __restrict__ wout) {
    int i = blockIdx.x * 256 + threadIdx.x;   // 0..49151
    {
        int n8p = i >> 10, rem = i & 1023;
        int step = rem >> 6, rem2 = rem & 63;
        int lane = rem2 >> 1, j = rem2 & 1;
        int h = n8p / 12, p = n8p % 12;
        int seg = p >> 2;
        int n = seg * 128 + h * 32 + (p & 3) * 8 + (lane >> 2);
        int k = step * 8 + (lane & 3) + 4 * j;
        g_wqkvF[i] = f2tf(wqkv[k * 384 + n]);
    }
    if (i < 16 * 16 * 64) {
        int n8 = i >> 10, rem = i & 1023;
        int step = rem >> 6, rem2 = rem & 63;
        int lane = rem2 >> 1, j = rem2 & 1;
        int n = n8 * 8 + (lane >> 2);
        int k = step * 8 + (lane & 3) + 4 * j;
        g_woutF[i] = f2tf(wout[k * 128 + n]);
    }
}

// ===========================================================================
// smem map (u32):
//  sQ 0..8704   sK 8704..17408   sV 17408..26112   (stride 136, paired)
//  sA 26112..34816  (P1 A; never overlaid — safe during head drift)
//  sP 34816..53248  (4 heads x [64][72]; holds O per head after phase E)
//  PE 53248  BO 53504   total 53632 u32 = 214528 B
// ===========================================================================
#define SQ_OFF 0
#define SK_OFF 8704
#define SV_OFF 17408
#define SA_OFF 26112
#define SP_OFF 34816
#define PE_OFF 53248
#define BO_OFF 53504
#define FU_SMEM (53632 * 4)

__global__ __launch_bounds__(512, 1)
void fused_kernel(const float* __restrict__ x,
                  const float* __restrict__ bout,
                  const float* __restrict__ pe,  const float* __restrict__ ul,
                  const float* __restrict__ lr,  float* __restrict__ out) {
    extern __shared__ uint32_t sm[];
    uint32_t* sQ = sm + SQ_OFF;
    uint32_t* sK = sm + SK_OFF;
    uint32_t* sV = sm + SV_OFF;
    uint32_t* sA = sm + SA_OFF;
    uint32_t* sP = sm + SP_OFF;
    float* sPE = (float*)(sm + PE_OFF);
    float* sBO = (float*)(sm + BO_OFF);

    const int t = threadIdx.x;
    const int warp = t >> 5, lane = t & 31;
    const int gid = lane >> 2, tid4 = lane & 3;
    const int blk = blockIdx.x;
    const int bb = blk >> 8, win = blk & 255;
    const int wy = win >> 4, wx = win & 15;

    // warp role: head h; P1 sub-tile (sm2 rows-half, sn2 cols-half);
    // attention q-row base wrb (16 rows per warp).
    const int head = warp >> 2, s = warp & 3;
    const int sm2 = s & 1, sn2 = s >> 1;
    const int rb2 = sm2 * 32;
    const int hoff = head * 32;
    const int wrb = s * 16;

    // c-frag (cols 2*tid4, 2*tid4+1) -> paired (col tid4, col tid4+4) via shfl
    auto pairFrag = [&](float v0, float v1, uint32_t& lo, uint32_t& hi) {
        uint32_t y0 = f2tf(v0), y1 = f2tf(v1);
        int src = (lane & ~3) | (tid4 >> 1);
        uint32_t p0 = __shfl_sync(0xffffffffu, y0, src);
        uint32_t p1 = __shfl_sync(0xffffffffu, y1, src);
        uint32_t q0 = __shfl_sync(0xffffffffu, y0, src + 2);
        uint32_t q1 = __shfl_sync(0xffffffffu, y1, src + 2);
        lo = (tid4 & 1) ? p1 : p0;
        hi = (tid4 & 1) ? q1 : q0;
    };

    // B fragment loader: 6 n8'-tiles of this warp's column half
    uint2 bA[12], bB[12];
    auto ldBkt = [&](uint2* dst, int kt) {
        #pragma unroll
        for (int kk = 0; kk < 2; kk++) {
            int step = kt * 2 + kk;
            #pragma unroll
            for (int nt = 0; nt < 6; nt++) {
                int n8p = head * 12 + sn2 * 6 + nt;
                dst[kk * 6 + nt] =
                    *(const uint2*)&g_wqkvF[(n8p * 16 + step) * 64 + lane * 2];
            }
        }
    };
    ldBkt(bA, 0);
    ldBkt(bB, 1);

    // ---- A gather: rolled x rows, tf32, pair-interleaved, packed STS.64 ----
    {
        const int row_a = t >> 3, part = t & 7;
        const int ty = row_a >> 3, tx = row_a & 7;
        const int sh = (wy * 8 + ty + 4) & 127, sw = (wx * 8 + tx + 4) & 127;
        const float* aptr = x + (((size_t)bb * 128 + sh) * 128 + sw) * 128 + part * 16;
        uint32_t* ap = sA + row_a * 136 + part * 16;
        float4 v0 = *(const float4*)(aptr + 0);
        float4 v1 = *(const float4*)(aptr + 4);
        float4 v2 = *(const float4*)(aptr + 8);
        float4 v3 = *(const float4*)(aptr + 12);
        *(uint2*)&ap[0]  = make_uint2(f2tf(v0.x), f2tf(v1.x));
        *(uint2*)&ap[2]  = make_uint2(f2tf(v0.y), f2tf(v1.y));
        *(uint2*)&ap[4]  = make_uint2(f2tf(v0.z), f2tf(v1.z));
        *(uint2*)&ap[6]  = make_uint2(f2tf(v0.w), f2tf(v1.w));
        *(uint2*)&ap[8]  = make_uint2(f2tf(v2.x), f2tf(v3.x));
        *(uint2*)&ap[10] = make_uint2(f2tf(v2.y), f2tf(v3.y));
        *(uint2*)&ap[12] = make_uint2(f2tf(v2.z), f2tf(v3.z));
        *(uint2*)&ap[14] = make_uint2(f2tf(v2.w), f2tf(v3.w));
    }
    if (t < 225) sPE[t] = pe[t];
    if (t < 128) sBO[t] = bout[t];
    __syncthreads();                         // [FULL SYNC 1] sA/sPE/sBO ready

    // ---- Phase 1: QKV slice GEMM, 32 rows x 48 cols per warp ----
    float acc[2][6][4];
    #pragma unroll
    for (int a = 0; a < 2; a++)
        #pragma unroll
        for (int b2 = 0; b2 < 6; b2++)
            #pragma unroll
            for (int c = 0; c < 4; c++) acc[a][b2][c] = 0.f;

    {
        const uint32_t* aR0 = &sA[(rb2 + gid) * 136 + 2 * tid4];
        const uint32_t* aR1 = aR0 + 8 * 136;
        const uint32_t* aR2 = aR0 + 16 * 136;
        const uint32_t* aR3 = aR0 + 24 * 136;
        #pragma unroll
        for (int step = 0; step < 16; step++) {
            const uint2* bfk = (((step >> 1) & 1) ? bB : bA) + (step & 1) * 6;
            uint2 a00 = *(const uint2*)(aR0 + step * 8);
            uint2 a01 = *(const uint2*)(aR1 + step * 8);
            uint2 a10 = *(const uint2*)(aR2 + step * 8);
            uint2 a11 = *(const uint2*)(aR3 + step * 8);
            uint32_t am0[4] = {a00.x, a01.x, a00.y, a01.y};
            uint32_t am1[4] = {a10.x, a11.x, a10.y, a11.y};
            #pragma unroll
            for (int nt = 0; nt < 6; nt++) {
                mma8(acc[0][nt], am0, (const uint32_t*)&bfk[nt]);
                mma8(acc[1][nt], am1, (const uint32_t*)&bfk[nt]);
            }
            if ((step & 1) == 1) {
                int kt = step >> 1;
                if (kt + 2 < 8) ldBkt((kt & 1) ? bB : bA, kt + 2);
            }
        }
    }

    // epilogue: write this warp's 48 cols x 32 rows into sQ/sK/sV (head-local)
    {
        const int s0 = SL(2 * tid4), s1 = SL(2 * tid4 + 1);
        #pragma unroll
        for (int mt = 0; mt < 2; mt++) {
            int r0 = rb2 + mt * 16 + gid, r1 = r0 + 8;
            #pragma unroll
            for (int nt = 0; nt < 6; nt++) {
                int p = sn2 * 6 + nt;
                int seg = p >> 2;
                int colbase = hoff + (p & 3) * 8;
                uint32_t* dst = sm + (seg == 0 ? SQ_OFF : seg == 1 ? SK_OFF : SV_OFF)
                                   + colbase;
                dst[r0 * 136 + s0] = f2tf(acc[mt][nt][0]);
                dst[r0 * 136 + s1] = f2tf(acc[mt][nt][1]);
                dst[r1 * 136 + s0] = f2tf(acc[mt][nt][2]);
                dst[r1 * 136 + s1] = f2tf(acc[mt][nt][3]);
            }
        }
    }
    // per-head barrier: head h's Q/K/V slice complete
    asm volatile("bar.sync %0, %1;" :: "r"(1 + head), "r"(128) : "memory");

    // ---- Phase B: S = Q K^T (4 warps/head, 16 q-rows each) ----
    float sacc[8][4];
    #pragma unroll
    for (int b2 = 0; b2 < 8; b2++)
        #pragma unroll
        for (int c = 0; c < 4; c++) sacc[b2][c] = 0.f;

    {
        const uint32_t* qR0 = &sQ[(wrb + gid) * 136 + hoff + 2 * tid4];
        const uint32_t* qR1 = qR0 + 8 * 136;
        const uint32_t* kB  = &sK[gid * 136 + hoff + 2 * tid4];
        #pragma unroll
        for (int kk = 0; kk < 32; kk += 8) {
            uint2 a0 = *(const uint2*)(qR0 + kk);
            uint2 a1 = *(const uint2*)(qR1 + kk);
            uint32_t a[4] = {a0.x, a1.x, a0.y, a1.y};
            #pragma unroll
            for (int nt = 0; nt < 8; nt++) {
                uint2 b = *(const uint2*)(kB + nt * (8 * 136) + kk);
                mma8(sacc[nt], a, (const uint32_t*)&b);
            }
        }
    }

    // ---- Phase C: bias + masks + softmax ----
    const float scale = 0.17677669529663689f;
    const bool addUL = (wy == 15);
    const bool addLR = (wx == 15);

    #pragma unroll
    for (int rh = 0; rh < 2; rh++) {
        const int i = wrb + rh * 8 + gid;
        const int iy = i >> 3, ix = i & 7;
        float vrow[16];
        float m = -1e30f;
        #pragma unroll
        for (int nt = 0; nt < 8; nt++) {
            #pragma unroll
            for (int u = 0; u < 2; u++) {
                int j = nt * 8 + tid4 * 2 + u;
                int jy = j >> 3, jx = j & 7;
                float v = sacc[nt][rh * 2 + u] * scale
                        + sPE[(jy - iy + 7) * 15 + (jx - ix + 7)];
                if (addUL) v += ul[i * 64 + j];
                if (addLR) v += lr[i * 64 + j];
                vrow[nt * 2 + u] = v;
                m = fmaxf(m, v);
            }
        }
        m = fmaxf(m, __shfl_xor_sync(0xffffffffu, m, 1));
        m = fmaxf(m, __shfl_xor_sync(0xffffffffu, m, 2));
        float sum = 0.f;
        #pragma unroll
        for (int u2 = 0; u2 < 16; u2++) {
            vrow[u2] = __expf(vrow[u2] - m);
            sum += vrow[u2];
        }
        sum += __shfl_xor_sync(0xffffffffu, sum, 1);
        sum += __shfl_xor_sync(0xffffffffu, sum, 2);
        float inv = 1.f / sum;
        #pragma unroll
        for (int nt = 0; nt < 8; nt++) {
            #pragma unroll
            for (int u = 0; u < 2; u++)
                sacc[nt][rh * 2 + u] = vrow[nt * 2 + u] * inv;
        }
    }
    // NOTE: no phase D — P stays in this warp's registers.

    // ---- Phase E: O = P @ V ; a-frags built from sacc via shfl ----
    float oacc[4][4];
    #pragma unroll
    for (int b2 = 0; b2 < 4; b2++)
        #pragma unroll
        for (int c = 0; c < 4; c++) oacc[b2][c] = 0.f;
    const int dslot = SL(gid);

    {
        const uint32_t* vB0 = &sV[tid4 * 136 + hoff + dslot];
        const uint32_t* vB1 = vB0 + 4 * 136;
        #pragma unroll
        for (int kk = 0; kk < 8; kk++) {
            uint32_t a[4];
            pairFrag(sacc[kk][0], sacc[kk][1], a[0], a[2]);   // row wrb+gid
            pairFrag(sacc[kk][2], sacc[kk][3], a[1], a[3]);   // row wrb+8+gid
            #pragma unroll
            for (int nt = 0; nt < 4; nt++) {
                uint32_t b[2];
                b[0] = vB0[kk * (8 * 136) + nt * 8];
                b[1] = vB1[kk * (8 * 136) + nt * 8];
                mma8(oacc[nt], a, b);
            }
        }
    }

    // ---- Phase F: store O into own rows of sP[head] ----
    uint32_t* myP = sP + head * (64 * 72);
    {
        const int s0 = SL(2 * tid4), s1 = SL(2 * tid4 + 1);
        #pragma unroll
        for (int nt = 0; nt < 4; nt++) {
            myP[(wrb + gid) * 72 + nt * 8 + s0]     = f2tf(oacc[nt][0]);
            myP[(wrb + gid) * 72 + nt * 8 + s1]     = f2tf(oacc[nt][1]);
            myP[(wrb + 8 + gid) * 72 + nt * 8 + s0] = f2tf(oacc[nt][2]);
            myP[(wrb + 8 + gid) * 72 + nt * 8 + s1] = f2tf(oacc[nt][3]);
        }
    }
    __syncthreads();                         // [FULL SYNC 2] all heads' O ready

    // ---- Phase G: Y = O @ w_out + b_out ----
    // O a-frag for k-step kk: head kk>>2, col-group kk&3, from sP region.
    const int pwm = warp & 3, pwn = warp >> 2;   // 4x4 grid, tile 16x32
    float yacc[4][4];
    #pragma unroll
    for (int b2 = 0; b2 < 4; b2++)
        #pragma unroll
        for (int c = 0; c < 4; c++) yacc[b2][c] = 0.f;

    uint2 wA[4], wB[4];
    auto ldW = [&](uint2* dst, int kk) {
        #pragma unroll
        for (int nt = 0; nt < 4; nt++) {
            int n8g = pwn * 4 + nt;
            dst[nt] = *(const uint2*)&g_woutF[(n8g * 16 + kk) * 64 + lane * 2];
        }
    };
    const uint32_t* oBase0 = sP + (pwm * 16 + gid) * 72 + 2 * tid4;
    const uint32_t* oBase1 = oBase0 + 8 * 72;
    auto ldOA = [&](uint2* d, int kk) {
        int off = (kk >> 2) * (64 * 72) + (kk & 3) * 8;
        d[0] = *(const uint2*)(oBase0 + off);
        d[1] = *(const uint2*)(oBase1 + off);
    };
    uint2 oaF[2][2];
    ldW(wA, 0);
    ldW(wB, 1);
    ldOA(oaF[0], 0);

    #pragma unroll
    for (int kk = 0; kk < 16; kk++) {
        if (kk + 1 < 16) ldOA(oaF[(kk + 1) & 1], kk + 1);
        const uint2* wf = (kk & 1) ? wB : wA;
        const uint2* af = oaF[kk & 1];
        uint32_t a[4] = {af[0].x, af[1].x, af[0].y, af[1].y};
        #pragma unroll
        for (int nt = 0; nt < 4; nt++)
            mma8(yacc[nt], a, (const uint32_t*)&wf[nt]);
        if (kk + 2 < 16) {
            if ((kk & 1) == 0) ldW(wA, kk + 2);
            else               ldW(wB, kk + 2);
        }
    }

    #pragma unroll
    for (int rh = 0; rh < 2; rh++) {
        int i = pwm * 16 + rh * 8 + gid;
        int ty = i >> 3, tx = i & 7;
        int h = (wy * 8 + ty + 4) & 127;
        int w = (wx * 8 + tx + 4) & 127;
        float* orow = out + (((size_t)bb * 128 + h) * 128 + w) * 128;
        #pragma unroll
        for (int nt = 0; nt < 4; nt++) {
            int c = pwn * 32 + nt * 8 + tid4 * 2;
            float2 v = make_float2(yacc[nt][rh * 2]     + sBO[c],
                                   yacc[nt][rh * 2 + 1] + sBO[c + 1]);
            *(float2*)(orow + c) = v;
        }
    }
}

// ===========================================================================
extern "C" void kernel_launch(void* const* d_in, const int* in_sizes, int n_in,
                              void* d_out, int out_size) {
    const float* x    = (const float*)d_in[0];
    const float* wqkv = (const float*)d_in[1];
    const float* wout = (const float*)d_in[2];
    const float* bout = (const float*)d_in[3];
    const float* pe   = (const float*)d_in[4];
    const float* ul   = (const float*)d_in[5];
    const float* lr   = (const float*)d_in[6];
    float* out = (float*)d_out;

    cudaFuncSetAttribute(fused_kernel, cudaFuncAttributeMaxDynamicSharedMemorySize, FU_SMEM);

    cvt_kernel<<<192, 256>>>(wqkv, wout);
    fused_kernel<<<4096, 512, FU_SMEM>>>(x, bout, pe, ul, lr, out);
}

// round 15
// speedup vs baseline: 1.0237x; 1.0237x over previous
#include <cuda_runtime.h>
#include <cstdint>

// ---------------------------------------------------------------------------
// WindowAttention (Swin-style), GB300 sm_103a — fused kernel, R15.
// Base = R13 (best: 358.7us). Change: weight arrays packed so ONE LDG.128
// per lane fetches B-fragments for TWO consecutive k-steps
// ([n8][step-pair][lane][4] = even j0, even j1, odd j0, odd j1).
// P1 B-LDGs halved (48->24/warp); phase-G weight LDGs halved.
// Head-decoupled P1 (per-warp head slice), per-head named barriers.
// ---------------------------------------------------------------------------

__device__ uint32_t g_wqkvF[48 * 16 * 64];   // head-major [n8'][sp][lane][4]
__device__ uint32_t g_woutF[16 * 16 * 64];   // [n8][sp][lane][4]

__device__ __forceinline__ uint32_t f2tf(float f) {
    uint32_t r;
    asm("cvt.rna.tf32.f32 %0, %1;" : "=r"(r) : "f"(f));
    return r;
}

__device__ __forceinline__ void mma8(float* c, const uint32_t* a, const uint32_t* b) {
    asm volatile(
        "mma.sync.aligned.m16n8k8.row.col.f32.tf32.tf32.f32 "
        "{%0,%1,%2,%3}, {%4,%5,%6,%7}, {%8,%9}, {%0,%1,%2,%3};\n"
        : "+f"(c[0]), "+f"(c[1]), "+f"(c[2]), "+f"(c[3])
        : "r"(a[0]), "r"(a[1]), "r"(a[2]), "r"(a[3]), "r"(b[0]), "r"(b[1]));
}
// slot within an 8-wide k-group: [k0 k4 k1 k5 k2 k6 k3 k7]
__device__ __forceinline__ int SL(int c) { return ((c & 3) << 1) | (c >> 2); }

// ===========================================================================
// cvt: weights -> tf32 fragment-PAIR-linear.
// word (n8', sp, lane, q):  step = sp*2 + (q>>1), j = q&1
//   wqkv head-major: h = n8'/12, p = n8'%12 (0-3 Q,4-7 K,8-11 V)
//     n = (p>>2)*128 + h*32 + (p&3)*8 + lane>>2,  k = step*8 + (lane&3) + 4*j
//   wout: n = n8*8 + lane>>2, same k.
// ===========================================================================
__global__ void cvt_kernel(const float* __restrict__ wqkv,
                           const float* __restrict__ wout) {
    int i = blockIdx.x * 256 + threadIdx.x;   // 0..49151
    {
        int n8p = i >> 10, rem = i & 1023;
        int sp = rem >> 7, rem2 = rem & 127;
        int lane = rem2 >> 2, q = rem2 & 3;
        int step = sp * 2 + (q >> 1), j = q & 1;
        int h = n8p / 12, p = n8p % 12;
        int seg = p >> 2;
        int n = seg * 128 + h * 32 + (p & 3) * 8 + (lane >> 2);
        int k = step * 8 + (lane & 3) + 4 * j;
        g_wqkvF[i] = f2tf(wqkv[k * 384 + n]);
    }
    if (i < 16 * 16 * 64) {
        int n8 = i >> 10, rem = i & 1023;
        int sp = rem >> 7, rem2 = rem & 127;
        int lane = rem2 >> 2, q = rem2 & 3;
        int step = sp * 2 + (q >> 1), j = q & 1;
        int n = n8 * 8 + (lane >> 2);
        int k = step * 8 + (lane & 3) + 4 * j;
        g_woutF[i] = f2tf(wout[k * 128 + n]);
    }
}

// ===========================================================================
// smem map (u32):
//  sQ 0..8704   sK 8704..17408   sV 17408..26112   (stride 136, paired)
//  sA 26112..34816  (P1 A; never overlaid — safe during head drift)
//  sP 34816..53248  (4 heads x [64][72]; per-head O overlays own P after E)
//  PE 53248  BO 53504   total 53632 u32 = 214528 B
// ===========================================================================
#define SQ_OFF 0
#define SK_OFF 8704
#define SV_OFF 17408
#define SA_OFF 26112
#define SP_OFF 34816
#define PE_OFF 53248
#define BO_OFF 53504
#define FU_SMEM (53632 * 4)

__global__ __launch_bounds__(512, 1)
void fused_kernel(const float* __restrict__ x,
                  const float* __restrict__ bout,
                  const float* __restrict__ pe,  const float* __restrict__ ul,
                  const float* __restrict__ lr,  float* __restrict__ out) {
    extern __shared__ uint32_t sm[];
    uint32_t* sQ = sm + SQ_OFF;
    uint32_t* sK = sm + SK_OFF;
    uint32_t* sV = sm + SV_OFF;
    uint32_t* sA = sm + SA_OFF;
    uint32_t* sP = sm + SP_OFF;
    float* sPE = (float*)(sm + PE_OFF);
    float* sBO = (float*)(sm + BO_OFF);

    const int t = threadIdx.x;
    const int warp = t >> 5, lane = t & 31;
    const int gid = lane >> 2, tid4 = lane & 3;
    const int blk = blockIdx.x;
    const int bb = blk >> 8, win = blk & 255;
    const int wy = win >> 4, wx = win & 15;

    // warp role: head h, sub-slice s (24 cols of the 96-col head block)
    const int head = warp >> 2, s = warp & 3;
    const int hoff = head * 32;
    const int wrb = s * 16;                  // attention q-row base

    // B fragment-pair loader: 3 n8'-tiles, one LDG.128 each (2 steps)
    uint4 bA[3], bB[3];
    auto ldBkt = [&](uint4* dst, int kt) {
        #pragma unroll
        for (int nt = 0; nt < 3; nt++) {
            int n8p = head * 12 + s * 3 + nt;
            dst[nt] = *(const uint4*)&g_wqkvF[((n8p * 8 + kt) * 32 + lane) * 4];
        }
    };
    ldBkt(bA, 0);
    ldBkt(bB, 1);

    // ---- A gather: rolled x rows, tf32, pair-interleaved, packed STS.64 ----
    {
        const int row_a = t >> 3, part = t & 7;
        const int ty = row_a >> 3, tx = row_a & 7;
        const int sh = (wy * 8 + ty + 4) & 127, sw = (wx * 8 + tx + 4) & 127;
        const float* aptr = x + (((size_t)bb * 128 + sh) * 128 + sw) * 128 + part * 16;
        uint32_t* ap = sA + row_a * 136 + part * 16;
        float4 v0 = *(const float4*)(aptr + 0);
        float4 v1 = *(const float4*)(aptr + 4);
        float4 v2 = *(const float4*)(aptr + 8);
        float4 v3 = *(const float4*)(aptr + 12);
        *(uint2*)&ap[0]  = make_uint2(f2tf(v0.x), f2tf(v1.x));
        *(uint2*)&ap[2]  = make_uint2(f2tf(v0.y), f2tf(v1.y));
        *(uint2*)&ap[4]  = make_uint2(f2tf(v0.z), f2tf(v1.z));
        *(uint2*)&ap[6]  = make_uint2(f2tf(v0.w), f2tf(v1.w));
        *(uint2*)&ap[8]  = make_uint2(f2tf(v2.x), f2tf(v3.x));
        *(uint2*)&ap[10] = make_uint2(f2tf(v2.y), f2tf(v3.y));
        *(uint2*)&ap[12] = make_uint2(f2tf(v2.z), f2tf(v3.z));
        *(uint2*)&ap[14] = make_uint2(f2tf(v2.w), f2tf(v3.w));
    }
    if (t < 225) sPE[t] = pe[t];
    if (t < 128) sBO[t] = bout[t];
    __syncthreads();                         // [FULL SYNC 1] sA/sPE/sBO ready

    // ---- Phase 1: QKV slice GEMM, 64 rows x 24 cols per warp ----
    float acc[4][3][4];
    #pragma unroll
    for (int a = 0; a < 4; a++)
        #pragma unroll
        for (int b2 = 0; b2 < 3; b2++)
            #pragma unroll
            for (int c = 0; c < 4; c++) acc[a][b2][c] = 0.f;

    {
        const uint32_t* aR = &sA[gid * 136 + 2 * tid4];
        #pragma unroll
        for (int step = 0; step < 16; step++) {
            const uint4* bbuf = ((step >> 1) & 1) ? bB : bA;
            uint2 ar[8];
            #pragma unroll
            for (int r = 0; r < 8; r++)
                ar[r] = *(const uint2*)(aR + r * (8 * 136) + step * 8);
            #pragma unroll
            for (int mt = 0; mt < 4; mt++) {
                uint32_t am[4] = {ar[2 * mt].x, ar[2 * mt + 1].x,
                                  ar[2 * mt].y, ar[2 * mt + 1].y};
                #pragma unroll
                for (int nt = 0; nt < 3; nt++)
                    mma8(acc[mt][nt], am,
                         (const uint32_t*)&bbuf[nt] + (step & 1) * 2);
            }
            if ((step & 1) == 1) {
                int kt = step >> 1;
                if (kt + 2 < 8) ldBkt((kt & 1) ? bB : bA, kt + 2);
            }
        }
    }

    // epilogue: write this warp's 24 cols into sQ/sK/sV (head-local)
    {
        const int s0 = SL(2 * tid4), s1 = SL(2 * tid4 + 1);
        #pragma unroll
        for (int mt = 0; mt < 4; mt++) {
            int r0 = mt * 16 + gid, r1 = r0 + 8;
            #pragma unroll
            for (int nt = 0; nt < 3; nt++) {
                int p = s * 3 + nt;
                int seg = p >> 2;
                int colbase = hoff + (p & 3) * 8;
                uint32_t* dst = sm + (seg == 0 ? SQ_OFF : seg == 1 ? SK_OFF : SV_OFF)
                                   + colbase;
                dst[r0 * 136 + s0] = f2tf(acc[mt][nt][0]);
                dst[r0 * 136 + s1] = f2tf(acc[mt][nt][1]);
                dst[r1 * 136 + s0] = f2tf(acc[mt][nt][2]);
                dst[r1 * 136 + s1] = f2tf(acc[mt][nt][3]);
            }
        }
    }
    // per-head barrier: head h's Q/K/V slice complete
    asm volatile("bar.sync %0, %1;" :: "r"(1 + head), "r"(128) : "memory");

    // ---- Phase B: S = Q K^T (4 warps/head, 16 q-rows each) ----
    float sacc[8][4];
    #pragma unroll
    for (int b2 = 0; b2 < 8; b2++)
        #pragma unroll
        for (int c = 0; c < 4; c++) sacc[b2][c] = 0.f;

    {
        const uint32_t* qR0 = &sQ[(wrb + gid) * 136 + hoff + 2 * tid4];
        const uint32_t* qR1 = qR0 + 8 * 136;
        const uint32_t* kB  = &sK[gid * 136 + hoff + 2 * tid4];
        #pragma unroll
        for (int kk = 0; kk < 32; kk += 8) {
            uint2 a0 = *(const uint2*)(qR0 + kk);
            uint2 a1 = *(const uint2*)(qR1 + kk);
            uint32_t a[4] = {a0.x, a1.x, a0.y, a1.y};
            #pragma unroll
            for (int nt = 0; nt < 8; nt++) {
                uint2 b = *(const uint2*)(kB + nt * (8 * 136) + kk);
                mma8(sacc[nt], a, (const uint32_t*)&b);
            }
        }
    }

    // ---- Phase C: bias + masks + softmax ----
    const float scale = 0.17677669529663689f;
    const bool addUL = (wy == 15);
    const bool addLR = (wx == 15);

    #pragma unroll
    for (int rh = 0; rh < 2; rh++) {
        const int i = wrb + rh * 8 + gid;
        const int iy = i >> 3, ix = i & 7;
        float vrow[16];
        float m = -1e30f;
        #pragma unroll
        for (int nt = 0; nt < 8; nt++) {
            #pragma unroll
            for (int u = 0; u < 2; u++) {
                int j = nt * 8 + tid4 * 2 + u;
                int jy = j >> 3, jx = j & 7;
                float v = sacc[nt][rh * 2 + u] * scale
                        + sPE[(jy - iy + 7) * 15 + (jx - ix + 7)];
                if (addUL) v += ul[i * 64 + j];
                if (addLR) v += lr[i * 64 + j];
                vrow[nt * 2 + u] = v;
                m = fmaxf(m, v);
            }
        }
        m = fmaxf(m, __shfl_xor_sync(0xffffffffu, m, 1));
        m = fmaxf(m, __shfl_xor_sync(0xffffffffu, m, 2));
        float sum = 0.f;
        #pragma unroll
        for (int u2 = 0; u2 < 16; u2++) {
            vrow[u2] = __expf(vrow[u2] - m);
            sum += vrow[u2];
        }
        sum += __shfl_xor_sync(0xffffffffu, sum, 1);
        sum += __shfl_xor_sync(0xffffffffu, sum, 2);
        float inv = 1.f / sum;
        #pragma unroll
        for (int nt = 0; nt < 8; nt++) {
            #pragma unroll
            for (int u = 0; u < 2; u++)
                sacc[nt][rh * 2 + u] = vrow[nt * 2 + u] * inv;
        }
    }

    // ---- Phase D: store P (tf32, paired) into sP[head] ----
    uint32_t* myP = sP + head * (64 * 72);
    {
        const int s0 = SL(2 * tid4), s1 = SL(2 * tid4 + 1);
        #pragma unroll
        for (int rh = 0; rh < 2; rh++) {
            int i = wrb + rh * 8 + gid;
            #pragma unroll
            for (int nt = 0; nt < 8; nt++) {
                myP[i * 72 + nt * 8 + s0] = f2tf(sacc[nt][rh * 2]);
                myP[i * 72 + nt * 8 + s1] = f2tf(sacc[nt][rh * 2 + 1]);
            }
        }
    }
    // per-head barrier: sP[head] coherent for the head's 4 warps
    asm volatile("bar.sync %0, %1;" :: "r"(1 + head), "r"(128) : "memory");

    // ---- Phase E: O = P @ V ----
    float oacc[4][4];
    #pragma unroll
    for (int b2 = 0; b2 < 4; b2++)
        #pragma unroll
        for (int c = 0; c < 4; c++) oacc[b2][c] = 0.f;
    const int dslot = SL(gid);

    {
        const uint32_t* pR0 = &myP[(wrb + gid) * 72 + 2 * tid4];
        const uint32_t* pR1 = pR0 + 8 * 72;
        const uint32_t* vB0 = &sV[tid4 * 136 + hoff + dslot];
        const uint32_t* vB1 = vB0 + 4 * 136;
        #pragma unroll
        for (int kk = 0; kk < 8; kk++) {
            uint2 a0 = *(const uint2*)(pR0 + kk * 8);
            uint2 a1 = *(const uint2*)(pR1 + kk * 8);
            uint32_t a[4] = {a0.x, a1.x, a0.y, a1.y};
            #pragma unroll
            for (int nt = 0; nt < 4; nt++) {
                uint32_t b[2];
                b[0] = vB0[kk * (8 * 136) + nt * 8];
                b[1] = vB1[kk * (8 * 136) + nt * 8];
                mma8(oacc[nt], a, b);
            }
        }
    }

    // ---- Phase F: store O into own rows of sP[head] (P dead for them) ----
    {
        const int s0 = SL(2 * tid4), s1 = SL(2 * tid4 + 1);
        #pragma unroll
        for (int nt = 0; nt < 4; nt++) {
            myP[(wrb + gid) * 72 + nt * 8 + s0]     = f2tf(oacc[nt][0]);
            myP[(wrb + gid) * 72 + nt * 8 + s1]     = f2tf(oacc[nt][1]);
            myP[(wrb + 8 + gid) * 72 + nt * 8 + s0] = f2tf(oacc[nt][2]);
            myP[(wrb + 8 + gid) * 72 + nt * 8 + s1] = f2tf(oacc[nt][3]);
        }
    }
    __syncthreads();                         // [FULL SYNC 2] all heads' O ready

    // ---- Phase G: Y = O @ w_out + b_out (paired weight LDG.128) ----
    const int pwm = warp & 3, pwn = warp >> 2;   // 4x4 grid, tile 16x32
    float yacc[4][4];
    #pragma unroll
    for (int b2 = 0; b2 < 4; b2++)
        #pragma unroll
        for (int c = 0; c < 4; c++) yacc[b2][c] = 0.f;

    uint4 wP[2][4];
    auto ldWp = [&](uint4* dst, int kp) {
        #pragma unroll
        for (int nt = 0; nt < 4; nt++) {
            int n8g = pwn * 4 + nt;
            dst[nt] = *(const uint4*)&g_woutF[((n8g * 8 + kp) * 32 + lane) * 4];
        }
    };
    const uint32_t* oBase0 = sP + (pwm * 16 + gid) * 72 + 2 * tid4;
    const uint32_t* oBase1 = oBase0 + 8 * 72;
    auto ldOA = [&](uint2* d, int kk) {
        int off = (kk >> 2) * (64 * 72) + (kk & 3) * 8;
        d[0] = *(const uint2*)(oBase0 + off);
        d[1] = *(const uint2*)(oBase1 + off);
    };
    uint2 oaF[2][2];
    ldWp(wP[0], 0);
    ldWp(wP[1], 1);
    ldOA(oaF[0], 0);

    #pragma unroll
    for (int kk = 0; kk < 16; kk++) {
        if (kk + 1 < 16) ldOA(oaF[(kk + 1) & 1], kk + 1);
        const uint4* wf = wP[(kk >> 1) & 1];
        const uint2* af = oaF[kk & 1];
        uint32_t a[4] = {af[0].x, af[1].x, af[0].y, af[1].y};
        #pragma unroll
        for (int nt = 0; nt < 4; nt++)
            mma8(yacc[nt], a, (const uint32_t*)&wf[nt] + (kk & 1) * 2);
        if ((kk & 1) == 1) {
            int kp = kk >> 1;
            if (kp + 2 < 8) ldWp(wP[kp & 1], kp + 2);
        }
    }

    #pragma unroll
    for (int rh = 0; rh < 2; rh++) {
        int i = pwm * 16 + rh * 8 + gid;
        int ty = i >> 3, tx = i & 7;
        int h = (wy * 8 + ty + 4) & 127;
        int w = (wx * 8 + tx + 4) & 127;
        float* orow = out + (((size_t)bb * 128 + h) * 128 + w) * 128;
        #pragma unroll
        for (int nt = 0; nt < 4; nt++) {
            int c = pwn * 32 + nt * 8 + tid4 * 2;
            float2 v = make_float2(yacc[nt][rh * 2]     + sBO[c],
                                   yacc[nt][rh * 2 + 1] + sBO[c + 1]);
            *(float2*)(orow + c) = v;
        }
    }
}

// ===========================================================================
extern "C" void kernel_launch(void* const* d_in, const int* in_sizes, int n_in,
                              void* d_out, int out_size) {
    const float* x    = (const float*)d_in[0];
    const float* wqkv = (const float*)d_in[1];
    const float* wout = (const float*)d_in[2];
    const float* bout = (const float*)d_in[3];
    const float* pe   = (const float*)d_in[4];
    const float* ul   = (const float*)d_in[5];
    const float* lr   = (const float*)d_in[6];
    float* out = (float*)d_out;

    cudaFuncSetAttribute(fused_kernel, cudaFuncAttributeMaxDynamicSharedMemorySize, FU_SMEM);

    cvt_kernel<<<192, 256>>>(wqkv, wout);
    fused_kernel<<<4096, 512, FU_SMEM>>>(x, bout, pe, ul, lr, out);
}

// round 16
// speedup vs baseline: 1.5114x; 1.4765x over previous
#include <cuda_runtime.h>
#include <cuda_fp16.h>
#include <cstdint>

// ---------------------------------------------------------------------------
// WindowAttention (Swin-style), GB300 sm_103a — fused kernel, R16.
// Structure = R13 (head-decoupled, 2 full + 2 named barriers).
// Datapath switched tf32/m16n8k8 -> f16/m16n8k16: half the mma count,
// half the smem fragment bytes. f16 mantissa (10b) == tf32 mantissa, and all
// values are O(1), so accuracy is preserved (~5e-4).
// Row layouts: 16-wide k-slot interleave [k0 k1 k8 k9 k2 k3 k10 k11 ...] so
// one LDS.64 yields a (a0,a2)-pair / (b0,b1)-pair. V stored transposed.
// ---------------------------------------------------------------------------

__device__ uint32_t g_wqkvF[48 * 8 * 64];   // head-major [n8'][step16][lane][2]
__device__ uint32_t g_woutF[16 * 8 * 64];

__device__ __forceinline__ uint32_t f2h2(float lo, float hi) {
    uint32_t r;
    asm("cvt.rn.f16x2.f32 %0, %1, %2;" : "=r"(r) : "f"(hi), "f"(lo));
    return r;
}

__device__ __forceinline__ void mma16(float* c, const uint32_t* a, const uint32_t* b) {
    asm volatile(
        "mma.sync.aligned.m16n8k16.row.col.f32.f16.f16.f32 "
        "{%0,%1,%2,%3}, {%4,%5,%6,%7}, {%8,%9}, {%0,%1,%2,%3};\n"
        : "+f"(c[0]), "+f"(c[1]), "+f"(c[2]), "+f"(c[3])
        : "r"(a[0]), "r"(a[1]), "r"(a[2]), "r"(a[3]), "r"(b[0]), "r"(b[1]));
}

// ===========================================================================
// cvt: weights -> f16 fragment-linear.
// word u32 idx = ((n8'*8 + step)*32 + lane)*2 + hw
//   k_lo = step*16 + 2*(lane&3) + hw*8, k_hi = k_lo+1  (hw=0 -> b0, hw=1 -> b1)
//   wqkv head-major: h=n8'/12, p=n8'%12 (0-3 Q,4-7 K,8-11 V)
//     n = (p>>2)*128 + h*32 + (p&3)*8 + (lane>>2)
//   wout: n = n8*8 + (lane>>2)
// ===========================================================================
__global__ void cvt_kernel(const float* __restrict__ wqkv,
                           const float* __restrict__ wout) {
    int w = blockIdx.x * 256 + threadIdx.x;   // 0..24575
    {
        int hw = w & 1, lane = (w >> 1) & 31, step = (w >> 6) & 7, n8p = w >> 9;
        int h = n8p / 12, p = n8p % 12;
        int n = (p >> 2) * 128 + h * 32 + (p & 3) * 8 + (lane >> 2);
        int k = step * 16 + 2 * (lane & 3) + hw * 8;
        g_wqkvF[w] = f2h2(wqkv[k * 384 + n], wqkv[(k + 1) * 384 + n]);
    }
    if (w < 16 * 8 * 64) {
        int hw = w & 1, lane = (w >> 1) & 31, step = (w >> 6) & 7, n8 = w >> 9;
        int n = n8 * 8 + (lane >> 2);
        int k = step * 16 + 2 * (lane & 3) + hw * 8;
        g_woutF[w] = f2h2(wout[k * 128 + n], wout[(k + 1) * 128 + n]);
    }
}

// ===========================================================================
// smem map (u32):
//  sQ  0..4608      [64 tok][144h]  (stride 72 u32)
//  sK  4608..9216   [64 tok][144h]
//  sVT 9216..14336  [128 d][80h]    transposed V (stride 40 u32)
//  sA  14336..18944 [64 row][144h]  (P1 A)
//  sO  18944..23552 [64 tok][144h]  (written in F, read in G)
//  sP  23552..33792 4 heads x [64 tok][80h]
//  PE  33792..34048   BO 34048..34176    total 34176 u32 = 136704 B
// ===========================================================================
#define SQ_OFF  0
#define SK_OFF  4608
#define SVT_OFF 9216
#define SA_OFF  14336
#define SO_OFF  18944
#define SP_OFF  23552
#define PE_OFF  33792
#define BO_OFF  34048
#define FU_SMEM (34176 * 4)

__global__ __launch_bounds__(512, 1)
void fused_kernel(const float* __restrict__ x,
                  const float* __restrict__ bout,
                  const float* __restrict__ pe,  const float* __restrict__ ul,
                  const float* __restrict__ lr,  float* __restrict__ out) {
    extern __shared__ uint32_t sm[];
    uint32_t* sQ  = sm + SQ_OFF;
    uint32_t* sK  = sm + SK_OFF;
    uint32_t* sVT = sm + SVT_OFF;
    uint32_t* sA  = sm + SA_OFF;
    uint32_t* sO  = sm + SO_OFF;
    uint32_t* sP  = sm + SP_OFF;
    float* sPE = (float*)(sm + PE_OFF);
    float* sBO = (float*)(sm + BO_OFF);

    const int t = threadIdx.x;
    const int warp = t >> 5, lane = t & 31;
    const int gid = lane >> 2, tid4 = lane & 3;
    const int blk = blockIdx.x;
    const int bb = blk >> 8, win = blk & 255;
    const int wy = win >> 4, wx = win & 15;

    // warp role: head h, sub-slice s (24 of the 96 head cols)
    const int head = warp >> 2, s = warp & 3;
    const int hoff = head * 32;
    const int wrb = s * 16;                  // attention q-row base

    // B fragment loader: 3 n8'-tiles, one LDG.64 (b0,b1) each
    uint2 bA[3], bB[3];
    auto ldBkt = [&](uint2* dst, int step) {
        #pragma unroll
        for (int nt = 0; nt < 3; nt++) {
            int n8p = head * 12 + s * 3 + nt;
            dst[nt] = *(const uint2*)&g_wqkvF[((n8p * 8 + step) * 32 + lane) * 2];
        }
    };
    ldBkt(bA, 0);
    ldBkt(bB, 1);

    // ---- A gather: rolled x rows -> f16 16-slot-interleaved rows ----
    {
        const int row_a = t >> 3, part = t & 7;
        const int ty = row_a >> 3, tx = row_a & 7;
        const int sh = (wy * 8 + ty + 4) & 127, sw = (wx * 8 + tx + 4) & 127;
        const float* aptr = x + (((size_t)bb * 128 + sh) * 128 + sw) * 128 + part * 16;
        float v[16];
        #pragma unroll
        for (int j4 = 0; j4 < 4; j4++) {
            float4 q4 = *(const float4*)(aptr + j4 * 4);
            v[j4 * 4 + 0] = q4.x; v[j4 * 4 + 1] = q4.y;
            v[j4 * 4 + 2] = q4.z; v[j4 * 4 + 3] = q4.w;
        }
        uint32_t* ap = sA + row_a * 72 + part * 8;
        uint4 w0, w1;
        w0.x = f2h2(v[0],  v[1]);  w0.y = f2h2(v[8],  v[9]);
        w0.z = f2h2(v[2],  v[3]);  w0.w = f2h2(v[10], v[11]);
        w1.x = f2h2(v[4],  v[5]);  w1.y = f2h2(v[12], v[13]);
        w1.z = f2h2(v[6],  v[7]);  w1.w = f2h2(v[14], v[15]);
        *(uint4*)&ap[0] = w0;
        *(uint4*)&ap[4] = w1;
    }
    if (t < 225) sPE[t] = pe[t];
    if (t < 128) sBO[t] = bout[t];
    __syncthreads();                         // [FULL SYNC 1]

    // ---- Phase 1: QKV slice GEMM, 64 rows x 24 cols per warp, 8 k16-steps ----
    float acc[4][3][4];
    #pragma unroll
    for (int a = 0; a < 4; a++)
        #pragma unroll
        for (int b2 = 0; b2 < 3; b2++)
            #pragma unroll
            for (int c = 0; c < 4; c++) acc[a][b2][c] = 0.f;

    {
        const uint32_t* aR = &sA[gid * 72 + 2 * tid4];
        #pragma unroll
        for (int step = 0; step < 8; step++) {
            const uint2* bf = (step & 1) ? bB : bA;
            uint2 ar[8];
            #pragma unroll
            for (int r = 0; r < 8; r++)
                ar[r] = *(const uint2*)(aR + r * (8 * 72) + step * 8);
            #pragma unroll
            for (int mt = 0; mt < 4; mt++) {
                uint32_t am[4] = {ar[2 * mt].x, ar[2 * mt + 1].x,
                                  ar[2 * mt].y, ar[2 * mt + 1].y};
                #pragma unroll
                for (int nt = 0; nt < 3; nt++)
                    mma16(acc[mt][nt], am, (const uint32_t*)&bf[nt]);
            }
            if (step + 2 < 8) ldBkt((step & 1) ? bB : bA, step + 2);
        }
    }

    // epilogue: Q,K -> row-major 16-slot rows; V -> transposed sVT
    {
        #pragma unroll
        for (int mt = 0; mt < 4; mt++) {
            int r0 = mt * 16 + gid, r1 = r0 + 8;
            #pragma unroll
            for (int nt = 0; nt < 3; nt++) {
                int p = s * 3 + nt;
                int seg = p >> 2;
                if (seg < 2) {
                    // u32 idx = row*72 + (2*head + ((p&3)>>1))*8 + 2*tid4 + (p&1)
                    uint32_t* dst = (seg == 0 ? sQ : sK);
                    int off = (2 * head + ((p & 3) >> 1)) * 8 + 2 * tid4 + (p & 1);
                    dst[r0 * 72 + off] = f2h2(acc[mt][nt][0], acc[mt][nt][1]);
                    dst[r1 * 72 + off] = f2h2(acc[mt][nt][2], acc[mt][nt][3]);
                } else {
                    // transposed: sVT[d][token-slot]
                    int d = hoff + (p & 3) * 8 + 2 * tid4;
                    int posg = 4 * (gid >> 1) + (gid & 1);
                    __half* vh = (__half*)sVT;
                    vh[d * 80 + mt * 16 + posg]           = __float2half_rn(acc[mt][nt][0]);
                    vh[(d + 1) * 80 + mt * 16 + posg]     = __float2half_rn(acc[mt][nt][1]);
                    vh[d * 80 + mt * 16 + posg + 2]       = __float2half_rn(acc[mt][nt][2]);
                    vh[(d + 1) * 80 + mt * 16 + posg + 2] = __float2half_rn(acc[mt][nt][3]);
                }
            }
        }
    }
    // per-head barrier: head h's Q/K/V slice complete
    asm volatile("bar.sync %0, %1;" :: "r"(1 + head), "r"(128) : "memory");

    // ---- Phase B: S = Q K^T (2 k16-steps) ----
    float sacc[8][4];
    #pragma unroll
    for (int b2 = 0; b2 < 8; b2++)
        #pragma unroll
        for (int c = 0; c < 4; c++) sacc[b2][c] = 0.f;

    #pragma unroll
    for (int st = 0; st < 2; st++) {
        int off = (2 * head + st) * 8 + 2 * tid4;
        uint2 a0 = *(const uint2*)&sQ[(wrb + gid) * 72 + off];
        uint2 a1 = *(const uint2*)&sQ[(wrb + 8 + gid) * 72 + off];
        uint32_t a[4] = {a0.x, a1.x, a0.y, a1.y};
        #pragma unroll
        for (int nt = 0; nt < 8; nt++) {
            uint2 b = *(const uint2*)&sK[(nt * 8 + gid) * 72 + off];
            mma16(sacc[nt], a, (const uint32_t*)&b);
        }
    }

    // ---- Phase C: bias + masks + softmax (unchanged math) ----
    const float scale = 0.17677669529663689f;
    const bool addUL = (wy == 15);
    const bool addLR = (wx == 15);

    #pragma unroll
    for (int rh = 0; rh < 2; rh++) {
        const int i = wrb + rh * 8 + gid;
        const int iy = i >> 3, ix = i & 7;
        float vrow[16];
        float m = -1e30f;
        #pragma unroll
        for (int nt = 0; nt < 8; nt++) {
            #pragma unroll
            for (int u = 0; u < 2; u++) {
                int j = nt * 8 + tid4 * 2 + u;
                int jy = j >> 3, jx = j & 7;
                float v = sacc[nt][rh * 2 + u] * scale
                        + sPE[(jy - iy + 7) * 15 + (jx - ix + 7)];
                if (addUL) v += ul[i * 64 + j];
                if (addLR) v += lr[i * 64 + j];
                vrow[nt * 2 + u] = v;
                m = fmaxf(m, v);
            }
        }
        m = fmaxf(m, __shfl_xor_sync(0xffffffffu, m, 1));
        m = fmaxf(m, __shfl_xor_sync(0xffffffffu, m, 2));
        float sum = 0.f;
        #pragma unroll
        for (int u2 = 0; u2 < 16; u2++) {
            vrow[u2] = __expf(vrow[u2] - m);
            sum += vrow[u2];
        }
        sum += __shfl_xor_sync(0xffffffffu, sum, 1);
        sum += __shfl_xor_sync(0xffffffffu, sum, 2);
        float inv = 1.f / sum;
        #pragma unroll
        for (int nt = 0; nt < 8; nt++) {
            #pragma unroll
            for (int u = 0; u < 2; u++)
                sacc[nt][rh * 2 + u] = vrow[nt * 2 + u] * inv;
        }
    }

    // ---- Phase D: store P (f16, 16-slot rows, stride 40 u32) ----
    uint32_t* myP = sP + head * (64 * 40);
    #pragma unroll
    for (int rh = 0; rh < 2; rh++) {
        int row = wrb + rh * 8 + gid;
        #pragma unroll
        for (int nt = 0; nt < 8; nt++) {
            myP[row * 40 + (nt >> 1) * 8 + 2 * tid4 + (nt & 1)] =
                f2h2(sacc[nt][rh * 2], sacc[nt][rh * 2 + 1]);
        }
    }
    // per-head barrier: sP[head] coherent
    asm volatile("bar.sync %0, %1;" :: "r"(1 + head), "r"(128) : "memory");

    // ---- Phase E: O = P @ V (4 k16-steps over 64 keys) ----
    float oacc[4][4];
    #pragma unroll
    for (int b2 = 0; b2 < 4; b2++)
        #pragma unroll
        for (int c = 0; c < 4; c++) oacc[b2][c] = 0.f;

    #pragma unroll
    for (int st = 0; st < 4; st++) {
        uint2 a0 = *(const uint2*)&myP[(wrb + gid) * 40 + st * 8 + 2 * tid4];
        uint2 a1 = *(const uint2*)&myP[(wrb + 8 + gid) * 40 + st * 8 + 2 * tid4];
        uint32_t a[4] = {a0.x, a1.x, a0.y, a1.y};
        #pragma unroll
        for (int nt = 0; nt < 4; nt++) {
            uint2 b = *(const uint2*)&sVT[(hoff + nt * 8 + gid) * 40 + st * 8 + 2 * tid4];
            mma16(oacc[nt], a, (const uint32_t*)&b);
        }
    }

    // ---- Phase F: store O into sO (row-major 16-slot, stride 72 u32) ----
    #pragma unroll
    for (int nt = 0; nt < 4; nt++) {
        int off = (2 * head + (nt >> 1)) * 8 + 2 * tid4 + (nt & 1);
        sO[(wrb + gid) * 72 + off]     = f2h2(oacc[nt][0], oacc[nt][1]);
        sO[(wrb + 8 + gid) * 72 + off] = f2h2(oacc[nt][2], oacc[nt][3]);
    }
    __syncthreads();                         // [FULL SYNC 2] all heads' O ready

    // ---- Phase G: Y = O @ w_out + b_out (8 k16-steps) ----
    const int pwm = warp & 3, pwn = warp >> 2;   // 4x4 grid, tile 16x32
    float yacc[4][4];
    #pragma unroll
    for (int b2 = 0; b2 < 4; b2++)
        #pragma unroll
        for (int c = 0; c < 4; c++) yacc[b2][c] = 0.f;

    uint2 wA[4], wB[4];
    auto ldW = [&](uint2* dst, int step) {
        #pragma unroll
        for (int nt = 0; nt < 4; nt++) {
            int n8g = pwn * 4 + nt;
            dst[nt] = *(const uint2*)&g_woutF[((n8g * 8 + step) * 32 + lane) * 2];
        }
    };
    ldW(wA, 0);
    ldW(wB, 1);

    const uint32_t* oR0 = &sO[(pwm * 16 + gid) * 72 + 2 * tid4];
    const uint32_t* oR1 = oR0 + 8 * 72;
    #pragma unroll
    for (int step = 0; step < 8; step++) {
        uint2 a0 = *(const uint2*)(oR0 + step * 8);
        uint2 a1 = *(const uint2*)(oR1 + step * 8);
        uint32_t a[4] = {a0.x, a1.x, a0.y, a1.y};
        const uint2* wf = (step & 1) ? wB : wA;
        #pragma unroll
        for (int nt = 0; nt < 4; nt++)
            mma16(yacc[nt], a, (const uint32_t*)&wf[nt]);
        if (step + 2 < 8) ldW((step & 1) ? wB : wA, step + 2);
    }

    #pragma unroll
    for (int rh = 0; rh < 2; rh++) {
        int i = pwm * 16 + rh * 8 + gid;
        int ty = i >> 3, tx = i & 7;
        int h = (wy * 8 + ty + 4) & 127;
        int w = (wx * 8 + tx + 4) & 127;
        float* orow = out + (((size_t)bb * 128 + h) * 128 + w) * 128;
        #pragma unroll
        for (int nt = 0; nt < 4; nt++) {
            int c = pwn * 32 + nt * 8 + tid4 * 2;
            float2 v = make_float2(yacc[nt][rh * 2]     + sBO[c],
                                   yacc[nt][rh * 2 + 1] + sBO[c + 1]);
            *(float2*)(orow + c) = v;
        }
    }
}

// ===========================================================================
extern "C" void kernel_launch(void* const* d_in, const int* in_sizes, int n_in,
                              void* d_out, int out_size) {
    const float* x    = (const float*)d_in[0];
    const float* wqkv = (const float*)d_in[1];
    const float* wout = (const float*)d_in[2];
    const float* bout = (const float*)d_in[3];
    const float* pe   = (const float*)d_in[4];
    const float* ul   = (const float*)d_in[5];
    const float* lr   = (const float*)d_in[6];
    float* out = (float*)d_out;

    cudaFuncSetAttribute(fused_kernel, cudaFuncAttributeMaxDynamicSharedMemorySize, FU_SMEM);

    cvt_kernel<<<96, 256>>>(wqkv, wout);
    fused_kernel<<<4096, 512, FU_SMEM>>>(x, bout, pe, ul, lr, out);
}